// round 2
// baseline (speedup 1.0000x reference)
#include <cuda_runtime.h>
#include <math.h>

// ---------------- problem constants ----------------
#define NN   10000
#define DD   15
#define EE   320
#define OUTD 30
#define E2   (320*320)

// ---------------- device scratch (no allocs allowed) ----------------
static __device__ float g_Fall[320*1920];     // fused QKV proj mats, 6 blocks of 320x320
static __device__ float g_biasAll[1920];
static __device__ float g_Gq[320*320];
static __device__ float g_Gkcat[640*320];     // [Gk_in ; Gk_out]
static __device__ float g_Gbig[641*320];      // [Gv_in ; Gv_out ; (cv_in-cv_out)]
static __device__ float g_WoW[320*32];        // fin_o_w^T @ W  (ld 30 used)
static __device__ float g_bW[32];
static __device__ float g_cq[320];
static __device__ float g_ckin[320];
static __device__ float g_ckout[320];
static __device__ float g_cvout[320];
static __device__ float g_XQKV[(size_t)NN*1920];
static __device__ float g_Og[(size_t)NN*32*320];
static __device__ float g_R[(size_t)NN*320];
static __device__ float g_S[(size_t)NN*640];
static __device__ float g_Wsum[(size_t)NN*641];
static __device__ float g_CTX[(size_t)NN*320];

// ---------------- generic tiled fp32 GEMM ----------------
// C[m,n] = sum_k Aop[m,k]*Bop[k,n] (+bias[n]) (+optional ELU)
// Aop = TRA ? A[k*lda+m] : A[m*lda+k];  Bop = TRB ? B[n*ldb+k] : B[k*ldb+n]
template<bool TRA, bool TRB, bool ELU>
__global__ void gemm_tiled(const float* __restrict__ A, int lda,
                           const float* __restrict__ B, int ldb,
                           const float* __restrict__ bias,
                           float* __restrict__ C, int ldc,
                           int M, int N, int K)
{
    __shared__ float As[16][68];
    __shared__ float Bs[16][68];
    const int tid = threadIdx.x;
    const int tx = tid & 15, ty = tid >> 4;
    const int bm = blockIdx.y * 64, bn = blockIdx.x * 64;
    float acc[4][4] = {};

    for (int k0 = 0; k0 < K; k0 += 16) {
        // --- load A tile into As[kk][mm] ---
        if (!TRA) {
            int kk = tid & 15, m0 = tid >> 4;
            #pragma unroll
            for (int i = 0; i < 4; i++) {
                int mm = m0 + i*16;
                int gm = bm + mm, gk = k0 + kk;
                As[kk][mm] = (gm < M && gk < K) ? A[(size_t)gm*lda + gk] : 0.f;
            }
        } else {
            int mm = tid & 63, kq = tid >> 6;
            #pragma unroll
            for (int i = 0; i < 4; i++) {
                int kk = kq + i*4;
                int gm = bm + mm, gk = k0 + kk;
                As[kk][mm] = (gm < M && gk < K) ? A[(size_t)gk*lda + gm] : 0.f;
            }
        }
        // --- load B tile into Bs[kk][nn] ---
        if (!TRB) {
            int nn = tid & 63, kq = tid >> 6;
            #pragma unroll
            for (int i = 0; i < 4; i++) {
                int kk = kq + i*4;
                int gk = k0 + kk, gn = bn + nn;
                Bs[kk][nn] = (gk < K && gn < N) ? B[(size_t)gk*ldb + gn] : 0.f;
            }
        } else {
            int kk = tid & 15, n0 = tid >> 4;
            #pragma unroll
            for (int i = 0; i < 4; i++) {
                int nn = n0 + i*16;
                int gk = k0 + kk, gn = bn + nn;
                Bs[kk][nn] = (gk < K && gn < N) ? B[(size_t)gn*ldb + gk] : 0.f;
            }
        }
        __syncthreads();
        #pragma unroll
        for (int kk = 0; kk < 16; kk++) {
            float4 a = *(const float4*)&As[kk][ty*4];
            float4 b = *(const float4*)&Bs[kk][tx*4];
            acc[0][0] += a.x*b.x; acc[0][1] += a.x*b.y; acc[0][2] += a.x*b.z; acc[0][3] += a.x*b.w;
            acc[1][0] += a.y*b.x; acc[1][1] += a.y*b.y; acc[1][2] += a.y*b.z; acc[1][3] += a.y*b.w;
            acc[2][0] += a.z*b.x; acc[2][1] += a.z*b.y; acc[2][2] += a.z*b.z; acc[2][3] += a.z*b.w;
            acc[3][0] += a.w*b.x; acc[3][1] += a.w*b.y; acc[3][2] += a.w*b.z; acc[3][3] += a.w*b.w;
        }
        __syncthreads();
    }
    #pragma unroll
    for (int i = 0; i < 4; i++) {
        int gm = bm + ty*4 + i;
        if (gm >= M) continue;
        #pragma unroll
        for (int j = 0; j < 4; j++) {
            int gn = bn + tx*4 + j;
            if (gn >= N) continue;
            float v = acc[i][j] + (bias ? bias[gn] : 0.f);
            if (ELU) v = (v > 0.f) ? v : (expf(v) - 1.f);
            C[(size_t)gm*ldc + gn] = v;
        }
    }
}

// ---------------- small vector prep ----------------
__global__ void prep_vectors(const float* __restrict__ in_qkv_b, const float* __restrict__ out_qkv_b,
                             const float* __restrict__ in_o_b, const float* __restrict__ out_o_b,
                             const float* __restrict__ fin_qkv_w, const float* __restrict__ fin_qkv_b,
                             const float* __restrict__ fin_o_b, const float* __restrict__ Wm)
{
    int b = blockIdx.x, t = threadIdx.x; // 320 threads
    if (b < 6) {
        int i = b*320 + t;
        g_biasAll[i] = (i < 960) ? in_qkv_b[i] : out_qkv_b[i - 960];
    } else if (b == 6) {            // cq = in_o_b @ fin_wq^T + fin_bq
        float s = fin_qkv_b[t];
        const float* w = fin_qkv_w;
        for (int k = 0; k < 320; k++) s += in_o_b[k] * w[t*320 + k];
        g_cq[t] = s;
    } else if (b == 7) {            // ck_in
        float s = fin_qkv_b[320 + t];
        const float* w = fin_qkv_w + E2;
        for (int k = 0; k < 320; k++) s += in_o_b[k] * w[t*320 + k];
        g_ckin[t] = s;
    } else if (b == 8) {            // ck_out
        float s = fin_qkv_b[320 + t];
        const float* w = fin_qkv_w + E2;
        for (int k = 0; k < 320; k++) s += out_o_b[k] * w[t*320 + k];
        g_ckout[t] = s;
    } else if (b == 9) {            // cv_out
        float s = fin_qkv_b[640 + t];
        const float* w = fin_qkv_w + 2*E2;
        for (int k = 0; k < 320; k++) s += out_o_b[k] * w[t*320 + k];
        g_cvout[t] = s;
    } else if (b == 10) {           // Gbig row 640 = (in_o_b - out_o_b) @ fin_wv^T
        float s = 0.f;
        const float* w = fin_qkv_w + 2*E2;
        for (int k = 0; k < 320; k++) s += (in_o_b[k] - out_o_b[k]) * w[t*320 + k];
        g_Gbig[640*320 + t] = s;
    } else if (b == 11) {           // bW = fin_o_b @ W
        if (t < OUTD) {
            float s = 0.f;
            for (int j = 0; j < 320; j++) s += fin_o_b[j] * Wm[j*OUTD + t];
            g_bW[t] = s;
        }
    }
}

// ---------------- per-node in/out attention (16 tokens, 5 heads, hd=64) ----------------
// grid (NN, 2): y = layer (0=in,1=out). 128 threads. Writes Og[node][layer*16 + l][e].
__global__ void attn_inout_kernel(const float* __restrict__ XQKV,
                                  const int* __restrict__ in_idx,
                                  const int* __restrict__ out_idx,
                                  float* __restrict__ Og)
{
    extern __shared__ float sm[];
    float* Qs = sm;                 // 16*324
    float* Ks = Qs + 16*324;
    float* Vs = Ks + 16*324;
    float* Asc = Vs + 16*324;       // 5*16*16
    int* tok = (int*)(Asc + 5*256); // 16

    const int node = blockIdx.x;
    const int layer = blockIdx.y;
    const int tid = threadIdx.x;
    const int* idx = layer ? out_idx : in_idx;
    const int qoff = layer * 960;

    if (tid < 16) tok[tid] = (tid == 0) ? node : idx[node*DD + tid - 1];
    __syncthreads();

    // gather Q/K/V rows (float4)
    for (int t = tid; t < 3*16*80; t += 128) {
        int mat = t / 1280;
        int rem = t - mat*1280;
        int r = rem / 80;
        int e4 = rem - r*80;
        float4 v = *(const float4*)(XQKV + (size_t)tok[r]*1920 + qoff + mat*320 + e4*4);
        *(float4*)(sm + mat*(16*324) + r*324 + e4*4) = v;
    }
    __syncthreads();

    // scores: thread t<80 -> head h, 4x4 (l,m) tile
    if (tid < 80) {
        int h = tid / 16;
        int lb = (tid & 15) >> 2;
        int mb = tid & 3;
        float s[4][4] = {};
        const float* qb = Qs + lb*4*324 + h*64;
        const float* kb = Ks + mb*4*324 + h*64;
        #pragma unroll
        for (int k4 = 0; k4 < 16; k4++) {
            float4 qv[4], kv[4];
            #pragma unroll
            for (int i = 0; i < 4; i++) qv[i] = *(const float4*)(qb + i*324 + k4*4);
            #pragma unroll
            for (int j = 0; j < 4; j++) kv[j] = *(const float4*)(kb + j*324 + k4*4);
            #pragma unroll
            for (int i = 0; i < 4; i++)
                #pragma unroll
                for (int j = 0; j < 4; j++)
                    s[i][j] += qv[i].x*kv[j].x + qv[i].y*kv[j].y + qv[i].z*kv[j].z + qv[i].w*kv[j].w;
        }
        #pragma unroll
        for (int i = 0; i < 4; i++)
            #pragma unroll
            for (int j = 0; j < 4; j++)
                Asc[h*256 + (lb*4+i)*16 + (mb*4+j)] = s[i][j] * 0.125f;
    }
    __syncthreads();

    // softmax per (h,l)
    if (tid < 80) {
        int h = tid / 16, l = tid & 15;
        float* row = Asc + h*256 + l*16;
        float mx = row[0];
        #pragma unroll
        for (int m = 1; m < 16; m++) mx = fmaxf(mx, row[m]);
        float e[16]; float ssum = 0.f;
        #pragma unroll
        for (int m = 0; m < 16; m++) { e[m] = __expf(row[m] - mx); ssum += e[m]; }
        float inv = 1.f / ssum;
        #pragma unroll
        for (int m = 0; m < 16; m++) row[m] = e[m] * inv;
    }
    __syncthreads();

    // O = A @ V  -> global (pre-output-projection; projection folded downstream)
    float* Ob = Og + ((size_t)node*32 + layer*16)*320;
    for (int it = tid; it < 160; it += 128) {
        int lb = it / 40, e8 = it - lb*40;
        int h = e8 >> 3;
        float acc[4][8] = {};
        #pragma unroll
        for (int m = 0; m < 16; m++) {
            const float* vp = Vs + m*324 + e8*8;
            float4 v0 = *(const float4*)vp;
            float4 v1 = *(const float4*)(vp + 4);
            #pragma unroll
            for (int i = 0; i < 4; i++) {
                float a = Asc[h*256 + (lb*4+i)*16 + m];
                acc[i][0] += a*v0.x; acc[i][1] += a*v0.y; acc[i][2] += a*v0.z; acc[i][3] += a*v0.w;
                acc[i][4] += a*v1.x; acc[i][5] += a*v1.y; acc[i][6] += a*v1.z; acc[i][7] += a*v1.w;
            }
        }
        #pragma unroll
        for (int i = 0; i < 4; i++) {
            float* op = Ob + (lb*4+i)*320 + e8*8;
            float4 o0 = make_float4(acc[i][0], acc[i][1], acc[i][2], acc[i][3]);
            float4 o1 = make_float4(acc[i][4], acc[i][5], acc[i][6], acc[i][7]);
            *(float4*)op = o0;
            *(float4*)(op + 4) = o1;
        }
    }
}

// ---------------- per-node final attention (scores, softmax, weighted sums) ----------------
// grid NN, 128 threads.
__global__ void fin_part1_kernel(const float* __restrict__ Og, const float* __restrict__ R,
                                 const float* __restrict__ S, float* __restrict__ Wsum)
{
    extern __shared__ float sm[];
    float* Os  = sm;             // 32*324
    float* Rs  = Os + 32*324;    // 320
    float* Ss  = Rs + 320;       // 640
    float* red = Ss + 640;       // 128
    float* aw  = red + 128;      // [0..31]=a, [32]=a_in_tot, [33]=d_in, [34]=d_out

    const int node = blockIdx.x;
    const int tid = threadIdx.x;

    for (int t = tid; t < 320; t += 128) Rs[t] = R[(size_t)node*320 + t];
    for (int t = tid; t < 640; t += 128) Ss[t] = S[(size_t)node*640 + t];
    for (int t = tid; t < 32*80; t += 128) {
        int r = t / 80, e4 = t - r*80;
        *(float4*)(Os + r*324 + e4*4) = *(const float4*)(Og + ((size_t)node*32 + r)*320 + e4*4);
    }
    __syncthreads();

    // 32 score dots, 4 threads each
    {
        int m = tid >> 2, s4 = tid & 3;
        const float* Sx = Ss + ((m < 16) ? 0 : 320);
        const float* Om = Os + m*324;
        float p = 0.f;
        for (int e = s4*80; e < s4*80 + 80; e++) p += Sx[e] * Om[e];
        red[tid] = p;
    }
    // d_in / d_out via warps 0,1
    if (tid < 64) {
        const float* ck = (tid < 32) ? g_ckin : g_ckout;
        int lane = tid & 31;
        float p = 0.f;
        for (int e = lane; e < 320; e += 32) p += Rs[e] * ck[e];
        #pragma unroll
        for (int o = 16; o; o >>= 1) p += __shfl_down_sync(0xffffffffu, p, o);
        if (lane == 0) aw[33 + (tid >> 5)] = p;
    }
    __syncthreads();

    // softmax over 32 (warp 0)
    if (tid < 32) {
        float sc = red[tid*4] + red[tid*4+1] + red[tid*4+2] + red[tid*4+3];
        sc += (tid < 16) ? aw[33] : aw[34];
        sc *= 0.0559016994f;  // 1/sqrt(320)
        float mx = sc;
        #pragma unroll
        for (int o = 16; o; o >>= 1) mx = fmaxf(mx, __shfl_xor_sync(0xffffffffu, mx, o));
        float ex = __expf(sc - mx);
        float ssum = ex;
        #pragma unroll
        for (int o = 16; o; o >>= 1) ssum += __shfl_xor_sync(0xffffffffu, ssum, o);
        float a = ex / ssum;
        aw[tid] = a;
        float ain = (tid < 16) ? a : 0.f;
        #pragma unroll
        for (int o = 16; o; o >>= 1) ain += __shfl_xor_sync(0xffffffffu, ain, o);
        if (tid == 0) aw[32] = ain;
    }
    __syncthreads();

    // weighted sums of O rows (in: m 0..15, out: m 16..31)
    for (int t = tid; t < 640; t += 128) {
        int which = t / 320, e = t - which*320;
        float acc = 0.f;
        #pragma unroll
        for (int m = 0; m < 16; m++) acc += aw[which*16 + m] * Os[(which*16 + m)*324 + e];
        Wsum[(size_t)node*641 + t] = acc;
    }
    if (tid == 0) Wsum[(size_t)node*641 + 640] = aw[32];
}

// ---------------- host launcher ----------------
extern "C" void kernel_launch(void* const* d_in, const int* in_sizes, int n_in,
                              void* d_out, int out_size)
{
    const float* X        = (const float*)d_in[0];
    const int*   in_idx   = (const int*)  d_in[1];
    const int*   out_idx  = (const int*)  d_in[2];
    const float* in_Wq    = (const float*)d_in[3];
    const float* in_Wk    = (const float*)d_in[4];
    const float* in_Wv    = (const float*)d_in[5];
    const float* in_qkv_w = (const float*)d_in[6];
    const float* in_qkv_b = (const float*)d_in[7];
    const float* in_o_w   = (const float*)d_in[8];
    const float* in_o_b   = (const float*)d_in[9];
    const float* out_Wq   = (const float*)d_in[10];
    const float* out_Wk   = (const float*)d_in[11];
    const float* out_Wv   = (const float*)d_in[12];
    const float* out_qkv_w= (const float*)d_in[13];
    const float* out_qkv_b= (const float*)d_in[14];
    const float* out_o_w  = (const float*)d_in[15];
    const float* out_o_b  = (const float*)d_in[16];
    const float* fin_qkv_w= (const float*)d_in[17];
    const float* fin_qkv_b= (const float*)d_in[18];
    const float* fin_o_w  = (const float*)d_in[19];
    const float* fin_o_b  = (const float*)d_in[20];
    const float* Wm       = (const float*)d_in[21];
    float* out = (float*)d_out;

    float *Fall, *biasAll, *Gq, *Gkcat, *Gbig, *WoW, *bW, *cq, *cvout;
    float *XQKV, *Og, *R, *S, *Wsum, *CTX;
    cudaGetSymbolAddress((void**)&Fall,   g_Fall);
    cudaGetSymbolAddress((void**)&biasAll,g_biasAll);
    cudaGetSymbolAddress((void**)&Gq,     g_Gq);
    cudaGetSymbolAddress((void**)&Gkcat,  g_Gkcat);
    cudaGetSymbolAddress((void**)&Gbig,   g_Gbig);
    cudaGetSymbolAddress((void**)&WoW,    g_WoW);
    cudaGetSymbolAddress((void**)&bW,     g_bW);
    cudaGetSymbolAddress((void**)&cq,     g_cq);
    cudaGetSymbolAddress((void**)&cvout,  g_cvout);
    cudaGetSymbolAddress((void**)&XQKV,   g_XQKV);
    cudaGetSymbolAddress((void**)&Og,     g_Og);
    cudaGetSymbolAddress((void**)&R,      g_R);
    cudaGetSymbolAddress((void**)&S,      g_S);
    cudaGetSymbolAddress((void**)&Wsum,   g_Wsum);
    cudaGetSymbolAddress((void**)&CTX,    g_CTX);

    const int attn_smem = (3*16*324 + 5*256)*4 + 16*4;
    const int fin_smem  = (32*324 + 320 + 640 + 128 + 40)*4;
    cudaFuncSetAttribute(attn_inout_kernel, cudaFuncAttributeMaxDynamicSharedMemorySize, attn_smem);
    cudaFuncSetAttribute(fin_part1_kernel,  cudaFuncAttributeMaxDynamicSharedMemorySize, fin_smem);

    dim3 blk(256);
    #define G64(M_, N_) dim3(((N_) + 63) / 64, ((M_) + 63) / 64)

    // small bias/vector prep
    prep_vectors<<<12, 320>>>(in_qkv_b, out_qkv_b, in_o_b, out_o_b,
                              fin_qkv_w, fin_qkv_b, fin_o_b, Wm);

    // fused QKV projection matrices: F = Wc @ w_part^T   (NT), into Fall columns
    gemm_tiled<false,true,false><<<G64(320,320), blk>>>(in_Wq, 320, in_qkv_w,        320, nullptr, Fall + 0,    1920, 320,320,320);
    gemm_tiled<false,true,false><<<G64(320,320), blk>>>(in_Wk, 320, in_qkv_w + E2,   320, nullptr, Fall + 320,  1920, 320,320,320);
    gemm_tiled<false,true,false><<<G64(320,320), blk>>>(in_Wv, 320, in_qkv_w + 2*E2, 320, nullptr, Fall + 640,  1920, 320,320,320);
    gemm_tiled<false,true,false><<<G64(320,320), blk>>>(out_Wq,320, out_qkv_w,       320, nullptr, Fall + 960,  1920, 320,320,320);
    gemm_tiled<false,true,false><<<G64(320,320), blk>>>(out_Wk,320, out_qkv_w + E2,  320, nullptr, Fall + 1280, 1920, 320,320,320);
    gemm_tiled<false,true,false><<<G64(320,320), blk>>>(out_Wv,320, out_qkv_w + 2*E2,320, nullptr, Fall + 1600, 1920, 320,320,320);
    // G matrices: o_w^T @ fin_w^T   (TT)
    gemm_tiled<true,true,false><<<G64(320,320), blk>>>(in_o_w, 320, fin_qkv_w,       320, nullptr, Gq,          320,  320,320,320);
    gemm_tiled<true,true,false><<<G64(320,320), blk>>>(in_o_w, 320, fin_qkv_w + E2,  320, nullptr, Gkcat,       320,  320,320,320);
    gemm_tiled<true,true,false><<<G64(320,320), blk>>>(out_o_w,320, fin_qkv_w + E2,  320, nullptr, Gkcat + E2,  320,  320,320,320);
    gemm_tiled<true,true,false><<<G64(320,320), blk>>>(in_o_w, 320, fin_qkv_w + 2*E2,320, nullptr, Gbig,        320,  320,320,320);
    gemm_tiled<true,true,false><<<G64(320,320), blk>>>(out_o_w,320, fin_qkv_w + 2*E2,320, nullptr, Gbig + E2,   320,  320,320,320);
    // WoW = fin_o_w^T @ W   (TN)
    gemm_tiled<true,false,false><<<G64(320,OUTD), blk>>>(fin_o_w, 320, Wm, OUTD, nullptr, WoW, OUTD, 320, OUTD, 320);

    // XQKV = X @ Fall + biasAll   [10000,1920]
    gemm_tiled<false,false,false><<<G64(NN,1920), blk>>>(X, 320, Fall, 1920, biasAll, XQKV, 1920, NN, 1920, 320);

    // per-node in/out attention -> Og [N,32,320]
    attn_inout_kernel<<<dim3(NN, 2), 128, attn_smem>>>(XQKV, in_idx, out_idx, Og);

    // R = Og[:,0,:] @ Gq + cq   (strided A, lda = 32*320)
    gemm_tiled<false,false,false><<<G64(NN,320), blk>>>(Og, 32*320, Gq, 320, cq, R, 320, NN, 320, 320);
    // S = R @ Gkcat^T   [10000,640]
    gemm_tiled<false,true,false><<<G64(NN,640), blk>>>(R, 320, Gkcat, 320, nullptr, S, 640, NN, 640, 320);

    // per-node final softmax + weighted sums -> Wsum [N,641]
    fin_part1_kernel<<<NN, 128, fin_smem>>>(Og, R, S, Wsum);

    // CTX = Wsum @ Gbig + cv_out   [10000,320], K=641
    gemm_tiled<false,false,false><<<G64(NN,320), blk>>>(Wsum, 641, Gbig, 320, cvout, CTX, 320, NN, 320, 641);

    // out = elu(CTX @ WoW + bW)   [10000,30]
    gemm_tiled<false,false,true><<<G64(NN,OUTD), blk>>>(CTX, 320, WoW, OUTD, bW, out, OUTD, NN, OUTD, 320);
}

// round 4
// speedup vs baseline: 1.2867x; 1.2867x over previous
#include <cuda_runtime.h>
#include <math.h>

// ---------------- problem constants ----------------
#define NN   10000
#define DD   15
#define EE   320
#define OUTD 30
#define E2   (320*320)
#define LDP  644   // padded ld for 642-col mats and Wsum(641)

// ---------------- device scratch (no allocs allowed) ----------------
static __device__ float g_Fall[320*1920];     // fused QKV proj mats, 6 blocks of 320x320
static __device__ float g_biasAll[1920];
static __device__ float g_Gq[E2];
static __device__ float g_Gkcat[640*320];     // [Gk_in ; Gk_out]
static __device__ float g_Gbig[641*320];      // [Gv_in ; Gv_out ; (cv_in-cv_out)]
static __device__ float g_WoW[320*32];        // fin_o_w^T @ W  (ld 32, 30 used)
static __device__ float g_cq[320];
static __device__ float g_ckin[320];
static __device__ float g_ckout[320];
static __device__ float g_cvout[320];
static __device__ float g_Bpack[320*LDP];     // [Gkcat^T | ckin | ckout], ld 644
static __device__ float g_Scoef[320*LDP];     // Gq @ Bpack, ld 644
static __device__ float g_GbW[641*32];        // Gbig @ WoW (ld 32, 30 used)
static __device__ float g_bS[642];            // cq @ Bpack
static __device__ float g_b2[32];             // cvout@WoW + fin_o_b@W
static __device__ float g_XQKV[(size_t)NN*1920];
static __device__ float g_Og[(size_t)NN*32*320];
static __device__ float g_S2[(size_t)NN*LDP]; // ld 644, 642 used
static __device__ float g_Wsum[(size_t)NN*LDP]; // ld 644, 641 used

// ---------------- big fp32 GEMM: 128x64 tile, 8x4 per thread ----------------
// C = A(MxK,row-major,lda) @ B(KxN,row-major,ldb) + bias (+ELU)
// REQUIREMENT: lda % 4 == 0 and ldb % 4 == 0 (float4 loads).
template<bool ELU>
__global__ __launch_bounds__(256)
void gemm128(const float* __restrict__ A, int lda,
             const float* __restrict__ B, int ldb,
             const float* __restrict__ bias,
             float* __restrict__ C, int ldc,
             int M, int N, int K)
{
    __shared__ float As[16][132];
    __shared__ float Bs[16][68];
    const int tid = threadIdx.x;
    const int tx = tid & 15, ty = tid >> 4;
    const int bm = blockIdx.y * 128, bn = blockIdx.x * 64;
    float acc[8][4] = {};

    for (int k0 = 0; k0 < K; k0 += 16) {
        // A tile: 128x16, 512 float4 tasks
        #pragma unroll
        for (int i = 0; i < 2; i++) {
            int idx = tid + i*256;
            int mm = idx >> 2, k4 = (idx & 3) * 4;
            int gm = bm + mm, gk = k0 + k4;
            float4 v = make_float4(0.f,0.f,0.f,0.f);
            if (gm < M) {
                const float* ap = A + (size_t)gm*lda + gk;
                if (gk + 3 < K) v = *(const float4*)ap;
                else {
                    if (gk+0 < K) v.x = ap[0];
                    if (gk+1 < K) v.y = ap[1];
                    if (gk+2 < K) v.z = ap[2];
                    if (gk+3 < K) v.w = ap[3];
                }
            }
            As[k4+0][mm] = v.x; As[k4+1][mm] = v.y;
            As[k4+2][mm] = v.z; As[k4+3][mm] = v.w;
        }
        // B tile: 16x64, 256 float4 tasks
        {
            int nn = (tid & 15) * 4, kk = tid >> 4;
            int gk = k0 + kk, gn = bn + nn;
            float4 v = make_float4(0.f,0.f,0.f,0.f);
            if (gk < K) {
                const float* bp = B + (size_t)gk*ldb + gn;
                if (gn + 3 < N) v = *(const float4*)bp;
                else {
                    if (gn+0 < N) v.x = bp[0];
                    if (gn+1 < N) v.y = bp[1];
                    if (gn+2 < N) v.z = bp[2];
                    if (gn+3 < N) v.w = bp[3];
                }
            }
            *(float4*)&Bs[kk][nn] = v;
        }
        __syncthreads();
        #pragma unroll
        for (int kk = 0; kk < 16; kk++) {
            float4 a0 = *(const float4*)&As[kk][ty*8];
            float4 a1 = *(const float4*)&As[kk][ty*8+4];
            float4 b  = *(const float4*)&Bs[kk][tx*4];
            float am[8] = {a0.x,a0.y,a0.z,a0.w,a1.x,a1.y,a1.z,a1.w};
            #pragma unroll
            for (int i = 0; i < 8; i++) {
                acc[i][0] += am[i]*b.x; acc[i][1] += am[i]*b.y;
                acc[i][2] += am[i]*b.z; acc[i][3] += am[i]*b.w;
            }
        }
        __syncthreads();
    }
    #pragma unroll
    for (int i = 0; i < 8; i++) {
        int gm = bm + ty*8 + i;
        if (gm >= M) continue;
        #pragma unroll
        for (int j = 0; j < 4; j++) {
            int gn = bn + tx*4 + j;
            if (gn >= N) continue;
            float v = acc[i][j] + (bias ? bias[gn] : 0.f);
            if (ELU) v = (v > 0.f) ? v : (expf(v) - 1.f);
            C[(size_t)gm*ldc + gn] = v;
        }
    }
}

// ---------------- batched weight-prep GEMM (64x64 tile, runtime tra/trb, scalar loads) ----------------
struct WDesc {
    const float* A; const float* B; float* C;
    int lda, ldb, ldc, M, N, K, tra, trb;
};
struct WDescArr { WDesc d[12]; };

__global__ __launch_bounds__(256)
void gemm_w_batched(WDescArr descs)
{
    const WDesc w = descs.d[blockIdx.z];
    __shared__ float As[16][68];
    __shared__ float Bs[16][68];
    const int tid = threadIdx.x;
    const int tx = tid & 15, ty = tid >> 4;
    const int bm = blockIdx.y * 64, bn = blockIdx.x * 64;
    if (bm >= w.M || bn >= w.N) return;
    float acc[4][4] = {};

    for (int k0 = 0; k0 < w.K; k0 += 16) {
        if (!w.tra) {
            int kk = tid & 15, m0 = tid >> 4;
            #pragma unroll
            for (int i = 0; i < 4; i++) {
                int mm = m0 + i*16;
                int gm = bm + mm, gk = k0 + kk;
                As[kk][mm] = (gm < w.M && gk < w.K) ? w.A[(size_t)gm*w.lda + gk] : 0.f;
            }
        } else {
            int mm = tid & 63, kq = tid >> 6;
            #pragma unroll
            for (int i = 0; i < 4; i++) {
                int kk = kq + i*4;
                int gm = bm + mm, gk = k0 + kk;
                As[kk][mm] = (gm < w.M && gk < w.K) ? w.A[(size_t)gk*w.lda + gm] : 0.f;
            }
        }
        if (!w.trb) {
            int nn = tid & 63, kq = tid >> 6;
            #pragma unroll
            for (int i = 0; i < 4; i++) {
                int kk = kq + i*4;
                int gk = k0 + kk, gn = bn + nn;
                Bs[kk][nn] = (gk < w.K && gn < w.N) ? w.B[(size_t)gk*w.ldb + gn] : 0.f;
            }
        } else {
            int kk = tid & 15, n0 = tid >> 4;
            #pragma unroll
            for (int i = 0; i < 4; i++) {
                int nn = n0 + i*16;
                int gk = k0 + kk, gn = bn + nn;
                Bs[kk][nn] = (gk < w.K && gn < w.N) ? w.B[(size_t)gn*w.ldb + gk] : 0.f;
            }
        }
        __syncthreads();
        #pragma unroll
        for (int kk = 0; kk < 16; kk++) {
            float4 a = *(const float4*)&As[kk][ty*4];
            float4 b = *(const float4*)&Bs[kk][tx*4];
            acc[0][0] += a.x*b.x; acc[0][1] += a.x*b.y; acc[0][2] += a.x*b.z; acc[0][3] += a.x*b.w;
            acc[1][0] += a.y*b.x; acc[1][1] += a.y*b.y; acc[1][2] += a.y*b.z; acc[1][3] += a.y*b.w;
            acc[2][0] += a.z*b.x; acc[2][1] += a.z*b.y; acc[2][2] += a.z*b.z; acc[2][3] += a.z*b.w;
            acc[3][0] += a.w*b.x; acc[3][1] += a.w*b.y; acc[3][2] += a.w*b.z; acc[3][3] += a.w*b.w;
        }
        __syncthreads();
    }
    #pragma unroll
    for (int i = 0; i < 4; i++) {
        int gm = bm + ty*4 + i;
        if (gm >= w.M) continue;
        #pragma unroll
        for (int j = 0; j < 4; j++) {
            int gn = bn + tx*4 + j;
            if (gn >= w.N) continue;
            w.C[(size_t)gm*w.ldc + gn] = acc[i][j];
        }
    }
}

// ---------------- small vector prep ----------------
__global__ void prep_vectors(const float* __restrict__ in_qkv_b, const float* __restrict__ out_qkv_b,
                             const float* __restrict__ in_o_b, const float* __restrict__ out_o_b,
                             const float* __restrict__ fin_qkv_w, const float* __restrict__ fin_qkv_b)
{
    int b = blockIdx.x, t = threadIdx.x; // 320 threads
    if (b < 6) {
        int i = b*320 + t;
        g_biasAll[i] = (i < 960) ? in_qkv_b[i] : out_qkv_b[i - 960];
    } else if (b == 6) {            // cq = in_o_b @ fin_wq^T + fin_bq
        float s = fin_qkv_b[t];
        const float* w = fin_qkv_w;
        for (int k = 0; k < 320; k++) s += in_o_b[k] * w[t*320 + k];
        g_cq[t] = s;
    } else if (b == 7) {            // ck_in
        float s = fin_qkv_b[320 + t];
        const float* w = fin_qkv_w + E2;
        for (int k = 0; k < 320; k++) s += in_o_b[k] * w[t*320 + k];
        g_ckin[t] = s;
    } else if (b == 8) {            // ck_out
        float s = fin_qkv_b[320 + t];
        const float* w = fin_qkv_w + E2;
        for (int k = 0; k < 320; k++) s += out_o_b[k] * w[t*320 + k];
        g_ckout[t] = s;
    } else if (b == 9) {            // cv_out
        float s = fin_qkv_b[640 + t];
        const float* w = fin_qkv_w + 2*E2;
        for (int k = 0; k < 320; k++) s += out_o_b[k] * w[t*320 + k];
        g_cvout[t] = s;
    } else if (b == 10) {           // Gbig row 640 = (in_o_b - out_o_b) @ fin_wv^T
        float s = 0.f;
        const float* w = fin_qkv_w + 2*E2;
        for (int k = 0; k < 320; k++) s += (in_o_b[k] - out_o_b[k]) * w[t*320 + k];
        g_Gbig[640*320 + t] = s;
    }
}

// Bpack[k][j] = Gkcat[j][k] (j<640) ; ckin[k] (j=640) ; ckout[k] (j=641); pad 642..643 = 0
__global__ void pack_B_kernel()
{
    int k = blockIdx.x;       // 0..319
    int j = threadIdx.x;      // 0..643 (644 threads)
    float v;
    if (j < 640)       v = g_Gkcat[(size_t)j*320 + k];
    else if (j == 640) v = g_ckin[k];
    else if (j == 641) v = g_ckout[k];
    else               v = 0.f;
    g_Bpack[(size_t)k*LDP + j] = v;
}

// bias vectors: bS[j] = cq @ Bpack[:,j] ; b2[j] = cvout@WoW[:,j] + fin_o_b@W[:,j]
__global__ void bias_kernel(const float* __restrict__ fin_o_b, const float* __restrict__ Wm)
{
    __shared__ float red[4];
    int b = blockIdx.x, t = threadIdx.x; // 128 threads
    float p = 0.f;
    if (b < 642) {
        for (int k = t; k < 320; k += 128) p += g_cq[k] * g_Bpack[(size_t)k*LDP + b];
    } else {
        int j = b - 642; // < 30
        for (int k = t; k < 320; k += 128)
            p += g_cvout[k] * g_WoW[k*32 + j] + fin_o_b[k] * Wm[k*OUTD + j];
    }
    #pragma unroll
    for (int o = 16; o; o >>= 1) p += __shfl_down_sync(0xffffffffu, p, o);
    if ((t & 31) == 0) red[t >> 5] = p;
    __syncthreads();
    if (t == 0) {
        float s = red[0] + red[1] + red[2] + red[3];
        if (b < 642) g_bS[b] = s; else g_b2[b - 642] = s;
    }
}

// ---------------- per-node in/out attention (16 tokens, 5 heads, hd=64) ----------------
__global__ void attn_inout_kernel(const float* __restrict__ XQKV,
                                  const int* __restrict__ in_idx,
                                  const int* __restrict__ out_idx,
                                  float* __restrict__ Og)
{
    extern __shared__ float sm[];
    float* Qs = sm;                 // 16*324
    float* Ks = Qs + 16*324;
    float* Vs = Ks + 16*324;
    float* Asc = Vs + 16*324;       // 5*16*16
    int* tok = (int*)(Asc + 5*256); // 16

    const int node = blockIdx.x;
    const int layer = blockIdx.y;
    const int tid = threadIdx.x;
    const int* idx = layer ? out_idx : in_idx;
    const int qoff = layer * 960;

    if (tid < 16) tok[tid] = (tid == 0) ? node : idx[node*DD + tid - 1];
    __syncthreads();

    for (int t = tid; t < 3*16*80; t += 128) {
        int mat = t / 1280;
        int rem = t - mat*1280;
        int r = rem / 80;
        int e4 = rem - r*80;
        float4 v = *(const float4*)(XQKV + (size_t)tok[r]*1920 + qoff + mat*320 + e4*4);
        *(float4*)(sm + mat*(16*324) + r*324 + e4*4) = v;
    }
    __syncthreads();

    if (tid < 80) {
        int h = tid / 16;
        int lb = (tid & 15) >> 2;
        int mb = tid & 3;
        float s[4][4] = {};
        const float* qb = Qs + lb*4*324 + h*64;
        const float* kb = Ks + mb*4*324 + h*64;
        #pragma unroll
        for (int k4 = 0; k4 < 16; k4++) {
            float4 qv[4], kv[4];
            #pragma unroll
            for (int i = 0; i < 4; i++) qv[i] = *(const float4*)(qb + i*324 + k4*4);
            #pragma unroll
            for (int j = 0; j < 4; j++) kv[j] = *(const float4*)(kb + j*324 + k4*4);
            #pragma unroll
            for (int i = 0; i < 4; i++)
                #pragma unroll
                for (int j = 0; j < 4; j++)
                    s[i][j] += qv[i].x*kv[j].x + qv[i].y*kv[j].y + qv[i].z*kv[j].z + qv[i].w*kv[j].w;
        }
        #pragma unroll
        for (int i = 0; i < 4; i++)
            #pragma unroll
            for (int j = 0; j < 4; j++)
                Asc[h*256 + (lb*4+i)*16 + (mb*4+j)] = s[i][j] * 0.125f;
    }
    __syncthreads();

    if (tid < 80) {
        int h = tid / 16, l = tid & 15;
        float* row = Asc + h*256 + l*16;
        float mx = row[0];
        #pragma unroll
        for (int m = 1; m < 16; m++) mx = fmaxf(mx, row[m]);
        float e[16]; float ssum = 0.f;
        #pragma unroll
        for (int m = 0; m < 16; m++) { e[m] = __expf(row[m] - mx); ssum += e[m]; }
        float inv = 1.f / ssum;
        #pragma unroll
        for (int m = 0; m < 16; m++) row[m] = e[m] * inv;
    }
    __syncthreads();

    float* Ob = Og + ((size_t)node*32 + layer*16)*320;
    for (int it = tid; it < 160; it += 128) {
        int lb = it / 40, e8 = it - lb*40;
        int h = e8 >> 3;
        float acc[4][8] = {};
        #pragma unroll
        for (int m = 0; m < 16; m++) {
            const float* vp = Vs + m*324 + e8*8;
            float4 v0 = *(const float4*)vp;
            float4 v1 = *(const float4*)(vp + 4);
            #pragma unroll
            for (int i = 0; i < 4; i++) {
                float a = Asc[h*256 + (lb*4+i)*16 + m];
                acc[i][0] += a*v0.x; acc[i][1] += a*v0.y; acc[i][2] += a*v0.z; acc[i][3] += a*v0.w;
                acc[i][4] += a*v1.x; acc[i][5] += a*v1.y; acc[i][6] += a*v1.z; acc[i][7] += a*v1.w;
            }
        }
        #pragma unroll
        for (int i = 0; i < 4; i++) {
            float* op = Ob + (lb*4+i)*320 + e8*8;
            *(float4*)op       = make_float4(acc[i][0], acc[i][1], acc[i][2], acc[i][3]);
            *(float4*)(op + 4) = make_float4(acc[i][4], acc[i][5], acc[i][6], acc[i][7]);
        }
    }
}

// ---------------- per-node final attention ----------------
// S2 row (ld 644): [0:320)=S_in, [320:640)=S_out, 640=d_in, 641=d_out
__global__ void fin_part1_kernel(const float* __restrict__ Og, const float* __restrict__ S2,
                                 float* __restrict__ Wsum)
{
    extern __shared__ float sm[];
    float* Os  = sm;             // 32*324
    float* Ss  = Os + 32*324;    // 644
    float* red = Ss + 644;       // 128
    float* aw  = red + 128;      // [0..31]=a, [32]=a_in_tot

    const int node = blockIdx.x;
    const int tid = threadIdx.x;

    for (int t = tid; t < 642; t += 128) Ss[t] = S2[(size_t)node*LDP + t];
    for (int t = tid; t < 32*80; t += 128) {
        int r = t / 80, e4 = t - r*80;
        *(float4*)(Os + r*324 + e4*4) = *(const float4*)(Og + ((size_t)node*32 + r)*320 + e4*4);
    }
    __syncthreads();

    // 32 score dots, 4 threads each
    {
        int m = tid >> 2, s4 = tid & 3;
        const float* Sx = Ss + ((m < 16) ? 0 : 320);
        const float* Om = Os + m*324;
        float p = 0.f;
        for (int e = s4*80; e < s4*80 + 80; e++) p += Sx[e] * Om[e];
        red[tid] = p;
    }
    __syncthreads();

    // softmax over 32 (warp 0)
    if (tid < 32) {
        float sc = red[tid*4] + red[tid*4+1] + red[tid*4+2] + red[tid*4+3];
        sc += (tid < 16) ? Ss[640] : Ss[641];
        sc *= 0.0559016994f;  // 1/sqrt(320)
        float mx = sc;
        #pragma unroll
        for (int o = 16; o; o >>= 1) mx = fmaxf(mx, __shfl_xor_sync(0xffffffffu, mx, o));
        float ex = __expf(sc - mx);
        float ssum = ex;
        #pragma unroll
        for (int o = 16; o; o >>= 1) ssum += __shfl_xor_sync(0xffffffffu, ssum, o);
        float a = ex / ssum;
        aw[tid] = a;
        float ain = (tid < 16) ? a : 0.f;
        #pragma unroll
        for (int o = 16; o; o >>= 1) ain += __shfl_xor_sync(0xffffffffu, ain, o);
        if (tid == 0) aw[32] = ain;
    }
    __syncthreads();

    // weighted sums of O rows
    for (int t = tid; t < 640; t += 128) {
        int which = t / 320, e = t - which*320;
        float acc = 0.f;
        #pragma unroll
        for (int m = 0; m < 16; m++) acc += aw[which*16 + m] * Os[(which*16 + m)*324 + e];
        Wsum[(size_t)node*LDP + t] = acc;
    }
    if (tid == 0) {
        Wsum[(size_t)node*LDP + 640] = aw[32];
        Wsum[(size_t)node*LDP + 641] = 0.f;
        Wsum[(size_t)node*LDP + 642] = 0.f;
        Wsum[(size_t)node*LDP + 643] = 0.f;
    }
}

// ---------------- host launcher ----------------
extern "C" void kernel_launch(void* const* d_in, const int* in_sizes, int n_in,
                              void* d_out, int out_size)
{
    const float* X        = (const float*)d_in[0];
    const int*   in_idx   = (const int*)  d_in[1];
    const int*   out_idx  = (const int*)  d_in[2];
    const float* in_Wq    = (const float*)d_in[3];
    const float* in_Wk    = (const float*)d_in[4];
    const float* in_Wv    = (const float*)d_in[5];
    const float* in_qkv_w = (const float*)d_in[6];
    const float* in_qkv_b = (const float*)d_in[7];
    const float* in_o_w   = (const float*)d_in[8];
    const float* in_o_b   = (const float*)d_in[9];
    const float* out_Wq   = (const float*)d_in[10];
    const float* out_Wk   = (const float*)d_in[11];
    const float* out_Wv   = (const float*)d_in[12];
    const float* out_qkv_w= (const float*)d_in[13];
    const float* out_qkv_b= (const float*)d_in[14];
    const float* out_o_w  = (const float*)d_in[15];
    const float* out_o_b  = (const float*)d_in[16];
    const float* fin_qkv_w= (const float*)d_in[17];
    const float* fin_qkv_b= (const float*)d_in[18];
    const float* fin_o_w  = (const float*)d_in[19];
    const float* fin_o_b  = (const float*)d_in[20];
    const float* Wm       = (const float*)d_in[21];
    float* out = (float*)d_out;

    float *Fall, *biasAll, *Gq, *Gkcat, *Gbig, *WoW, *cq, *cvout;
    float *Bpack, *Scoef, *GbW, *bS, *b2;
    float *XQKV, *Og, *S2, *Wsum;
    cudaGetSymbolAddress((void**)&Fall,   g_Fall);
    cudaGetSymbolAddress((void**)&biasAll,g_biasAll);
    cudaGetSymbolAddress((void**)&Gq,     g_Gq);
    cudaGetSymbolAddress((void**)&Gkcat,  g_Gkcat);
    cudaGetSymbolAddress((void**)&Gbig,   g_Gbig);
    cudaGetSymbolAddress((void**)&WoW,    g_WoW);
    cudaGetSymbolAddress((void**)&cq,     g_cq);
    cudaGetSymbolAddress((void**)&cvout,  g_cvout);
    cudaGetSymbolAddress((void**)&Bpack,  g_Bpack);
    cudaGetSymbolAddress((void**)&Scoef,  g_Scoef);
    cudaGetSymbolAddress((void**)&GbW,    g_GbW);
    cudaGetSymbolAddress((void**)&bS,     g_bS);
    cudaGetSymbolAddress((void**)&b2,     g_b2);
    cudaGetSymbolAddress((void**)&XQKV,   g_XQKV);
    cudaGetSymbolAddress((void**)&Og,     g_Og);
    cudaGetSymbolAddress((void**)&S2,     g_S2);
    cudaGetSymbolAddress((void**)&Wsum,   g_Wsum);

    const int attn_smem = (3*16*324 + 5*256)*4 + 16*4;
    const int fin_smem  = (32*324 + 644 + 128 + 40)*4;
    cudaFuncSetAttribute(attn_inout_kernel, cudaFuncAttributeMaxDynamicSharedMemorySize, attn_smem);
    cudaFuncSetAttribute(fin_part1_kernel,  cudaFuncAttributeMaxDynamicSharedMemorySize, fin_smem);

    // 1) small vector prep
    prep_vectors<<<11, 320>>>(in_qkv_b, out_qkv_b, in_o_b, out_o_b, fin_qkv_w, fin_qkv_b);

    // 2) ALL weight-prep GEMMs in one batched launch (12 descriptors)
    WDescArr wd;
    const float* Wc[6]  = {in_Wq, in_Wk, in_Wv, out_Wq, out_Wk, out_Wv};
    const float* Wp[6]  = {in_qkv_w, in_qkv_w + E2, in_qkv_w + 2*E2,
                           out_qkv_w, out_qkv_w + E2, out_qkv_w + 2*E2};
    for (int i = 0; i < 6; i++)
        wd.d[i] = WDesc{Wc[i], Wp[i], Fall + i*320, 320, 320, 1920, 320, 320, 320, 0, 1};
    wd.d[6]  = WDesc{in_o_w,  fin_qkv_w,        Gq,        320, 320, 320, 320, 320, 320, 1, 1};
    wd.d[7]  = WDesc{in_o_w,  fin_qkv_w + E2,   Gkcat,     320, 320, 320, 320, 320, 320, 1, 1};
    wd.d[8]  = WDesc{out_o_w, fin_qkv_w + E2,   Gkcat+E2,  320, 320, 320, 320, 320, 320, 1, 1};
    wd.d[9]  = WDesc{in_o_w,  fin_qkv_w + 2*E2, Gbig,      320, 320, 320, 320, 320, 320, 1, 1};
    wd.d[10] = WDesc{out_o_w, fin_qkv_w + 2*E2, Gbig+E2,   320, 320, 320, 320, 320, 320, 1, 1};
    // WoW = fin_o_w^T @ W  (TN), stored with ld 32
    wd.d[11] = WDesc{fin_o_w, Wm, WoW, 320, OUTD, 32, 320, OUTD, 320, 1, 0};
    gemm_w_batched<<<dim3(5, 5, 12), 256>>>(wd);

    // 3) pack B for Scoef (ld 644)
    pack_B_kernel<<<320, LDP>>>();

    // 4) Scoef = Gq @ Bpack   [320,642] (ld 644)
    gemm128<false><<<dim3(11, 3), 256>>>(Gq, 320, Bpack, LDP, nullptr, Scoef, LDP, 320, 642, 320);
    // 5) GbW = Gbig @ WoW     [641,30] (WoW ld 32, GbW ld 32)
    gemm128<false><<<dim3(1, 6), 256>>>(Gbig, 320, WoW, 32, nullptr, GbW, 32, 641, OUTD, 320);
    // 6) bias vectors
    bias_kernel<<<672, 128>>>(fin_o_b, Wm);

    // 7) XQKV = X @ Fall + biasAll   [10000,1920]
    gemm128<false><<<dim3(30, 79), 256>>>(X, 320, Fall, 1920, biasAll, XQKV, 1920, NN, 1920, 320);

    // 8) per-node in/out attention -> Og [N,32,320]
    attn_inout_kernel<<<dim3(NN, 2), 128, attn_smem>>>(XQKV, in_idx, out_idx, Og);

    // 9) S2 = O0_in @ Scoef + bS   [10000,642] (A strided over Og, lda=32*320; Scoef ld 644)
    gemm128<false><<<dim3(11, 79), 256>>>(Og, 32*320, Scoef, LDP, bS, S2, LDP, NN, 642, 320);

    // 10) per-node final softmax + weighted sums -> Wsum [N,641] (ld 644)
    fin_part1_kernel<<<NN, 128, fin_smem>>>(Og, S2, Wsum);

    // 11) out = elu(Wsum @ GbW + b2)   [10000,30] (Wsum ld 644, GbW ld 32, K=641)
    gemm128<true><<<dim3(1, 79), 256>>>(Wsum, LDP, GbW, 32, b2, out, OUTD, NN, OUTD, 641);
}